// round 2
// baseline (speedup 1.0000x reference)
#include <cuda_runtime.h>
#include <cuda_bf16.h>
#include <math.h>

// ---------------------------------------------------------------------------
// Problem dims
// ---------------------------------------------------------------------------
#define LQ   4096            // L = 16*16*16
#define NC   128             // channels C
#define DI   256             // D_INNER
#define NSEQ 3               // directions
#define NROW (NSEQ*LQ)       // 12288
#define DST  16              // D_STATE
#define NCHUNK 32            // chunks per sequence
#define CHUNK  128           // chunk length

// ---------------------------------------------------------------------------
// Workspace (static device allocations — permitted; no cudaMalloc anywhere)
// ---------------------------------------------------------------------------
__device__ float g_norm[LQ * NC];            // double-LN'd input, [voxel][c]
__device__ float g_xz  [NROW * 512];         // in_proj output
__device__ float g_xc  [NROW * DI];          // conv+silu output (u)
__device__ float g_xdbl[NROW * 40];          // x_proj output (dt|B|C)
__device__ float g_e1  [NROW * DI];          // exp(-delta)
__device__ float g_du  [NROW * DI];          // delta * u
__device__ float g_sz  [NROW * DI];          // silu(z)
__device__ float g_S   [NSEQ * NCHUNK * DI * DST];  // chunk local end-state
__device__ float g_p   [NSEQ * NCHUNK * DI];        // chunk prod of e1
__device__ float g_h0  [NSEQ * NCHUNK * DI * DST];  // chunk init state
__device__ float g_yg  [NROW * DI];          // gated scan output
__device__ float g_y   [NROW * NC];          // out_proj output
__device__ float g_res [LQ * NC];            // residual (x + proj out), [voxel][c]
__device__ float g_hn  [LQ * NC];            // LN(res)
__device__ float g_fc1 [LQ * 512];           // fc1+gelu output

// ---------------------------------------------------------------------------
// Helpers
// ---------------------------------------------------------------------------
__device__ __forceinline__ float fast_exp(float x) {
    // FMA-pipe-only exp (avoid MUFU). ~1e-7 rel error over clamped range.
    x = fminf(fmaxf(x, -87.0f), 87.0f);
    float t = x * 1.4426950408889634f;
    float n = rintf(t);
    float f = t - n;
    float g = f * 0.6931471805599453f;
    float p = 1.0f + g * (1.0f + g * (0.5f + g * (0.16666667f + g * (0.041666668f +
              g * (0.008333334f + g * 0.0013888889f)))));
    float s = __int_as_float(((int)n + 127) << 23);
    return p * s;
}

__device__ __forceinline__ float softplusf_(float x) {
    if (x > 15.0f) return x;
    float y = fast_exp(x);
    if (y < 0.05f) {
        // log1p(y) Taylor, |err| < 3e-9 at y=0.05
        return y * (1.0f + y * (-0.5f + y * (0.33333334f + y * (-0.25f + y * 0.2f))));
    }
    return log1pf(y);
}

__device__ __forceinline__ float wsum(float v) {
    #pragma unroll
    for (int o = 16; o > 0; o >>= 1) v += __shfl_xor_sync(0xffffffffu, v, o);
    return v;
}

// log-depth power table e[0..16] = e1^j
__device__ __forceinline__ void build_pows(float e1, float* e) {
    e[0] = 1.0f; e[1] = e1;
    #pragma unroll
    for (int j = 2; j <= 16; j++) e[j] = e[j >> 1] * e[j - (j >> 1)];
}

// ---------------------------------------------------------------------------
// K1: channels-first LN (eps 1e-6, ln_w/ln_b) then LN again (eps 1e-5, mnorm)
// Input x is [c][voxel]; output g_norm is [voxel][c]. One warp per voxel.
// ---------------------------------------------------------------------------
__global__ void ln_in_kernel(const float* __restrict__ x,
                             const float* __restrict__ lw, const float* __restrict__ lb,
                             const float* __restrict__ mw, const float* __restrict__ mb,
                             float* __restrict__ out) {
    int v = (blockIdx.x * blockDim.x + threadIdx.x) >> 5;
    int lane = threadIdx.x & 31;
    float vals[4]; float s1 = 0.f, s2 = 0.f;
    #pragma unroll
    for (int i = 0; i < 4; i++) {
        int c = lane + (i << 5);
        float t = x[c * LQ + v];
        vals[i] = t; s1 += t; s2 += t * t;
    }
    s1 = wsum(s1); s2 = wsum(s2);
    float m = s1 * (1.f / 128.f);
    float var = s2 * (1.f / 128.f) - m * m;
    float rs = rsqrtf(var + 1e-6f);
    float t1 = 0.f, t2 = 0.f; float yv[4];
    #pragma unroll
    for (int i = 0; i < 4; i++) {
        int c = lane + (i << 5);
        float yy = (vals[i] - m) * rs * lw[c] + lb[c];
        yv[i] = yy; t1 += yy; t2 += yy * yy;
    }
    t1 = wsum(t1); t2 = wsum(t2);
    float m2 = t1 * (1.f / 128.f);
    float v2 = t2 * (1.f / 128.f) - m2 * m2;
    float rs2 = rsqrtf(v2 + 1e-5f);
    #pragma unroll
    for (int i = 0; i < 4; i++) {
        int c = lane + (i << 5);
        out[v * NC + c] = (yv[i] - m2) * rs2 * mw[c] + mb[c];
    }
}

// K11: LN over rows of g_res (row-major [voxel][c]), eps 1e-6, ln_w/ln_b
__global__ void ln_row_kernel(const float* __restrict__ in,
                              const float* __restrict__ lw, const float* __restrict__ lb,
                              float* __restrict__ out) {
    int v = (blockIdx.x * blockDim.x + threadIdx.x) >> 5;
    int lane = threadIdx.x & 31;
    float vals[4]; float s1 = 0.f, s2 = 0.f;
    #pragma unroll
    for (int i = 0; i < 4; i++) {
        int c = lane + (i << 5);
        float t = in[v * NC + c];
        vals[i] = t; s1 += t; s2 += t * t;
    }
    s1 = wsum(s1); s2 = wsum(s2);
    float m = s1 * (1.f / 128.f);
    float var = s2 * (1.f / 128.f) - m * m;
    float rs = rsqrtf(var + 1e-6f);
    #pragma unroll
    for (int i = 0; i < 4; i++) {
        int c = lane + (i << 5);
        out[v * NC + c] = (vals[i] - m) * rs * lw[c] + lb[c];
    }
}

// ---------------------------------------------------------------------------
// Generic fp32 GEMM:  C[M,N] = A[M,K] * W[N,K]^T  (both K-contiguous)
// BM=BN=64, BK=16, 256 threads, 4x4 microtile. A via loader functor (gathers),
// epilogue functor fuses bias/activation/residual/transpose.
// M must be a multiple of 64, K a multiple of 16; N guarded.
// ---------------------------------------------------------------------------
struct ALoadDirect {
    const float* A; int K4;
    __device__ __forceinline__ float4 load(int row, int k4) const {
        return reinterpret_cast<const float4*>(A)[row * K4 + k4];
    }
};
struct ALoadNormGather {   // rows = r*4096 + l ; gather voxel per direction
    const float* A;
    __device__ __forceinline__ float4 load(int row, int k4) const {
        int r = row >> 12, l = row & 4095, v;
        if (r == 0)      v = l;
        else if (r == 1) v = ((l & 15) << 8) | (((l >> 8) & 15) << 4) | ((l >> 4) & 15);
        else             v = (((l >> 4) & 15) << 8) | ((l & 15) << 4) | ((l >> 8) & 15);
        return reinterpret_cast<const float4*>(A + (v << 7))[k4];
    }
};
struct ALoadCat {          // rows = voxel ; k = r*128 + c from g_y[(r,voxel),c]
    const float* Y;
    __device__ __forceinline__ float4 load(int row, int k4) const {
        int r = k4 >> 5, c4 = k4 & 31;
        return reinterpret_cast<const float4*>(Y + ((r << 12) + row) * NC)[c4];
    }
};

struct EpiStore {
    float* C; int stride;
    __device__ __forceinline__ void run(int row, int col, float v) const {
        C[row * stride + col] = v;
    }
};
struct EpiProjRes {        // + proj_b + x residual (x is [c][voxel])
    float* res; const float* bias; const float* x;
    __device__ __forceinline__ void run(int row, int col, float v) const {
        res[row * NC + col] = v + bias[col] + x[(col << 12) + row];
    }
};
struct EpiBiasGelu {
    float* C; const float* bias;
    __device__ __forceinline__ void run(int row, int col, float v) const {
        float g = v + bias[col];
        C[row * 512 + col] = 0.5f * g * (1.0f + erff(g * 0.70710678118654752f));
    }
};
struct EpiFc2 {            // + fc2_b + res residual, write channel-major output
    float* out; const float* bias; const float* res;
    __device__ __forceinline__ void run(int row, int col, float v) const {
        out[(col << 12) + row] = v + bias[col] + res[row * NC + col];
    }
};

template <class AL, class EP>
__global__ void __launch_bounds__(256) gemm_k(AL al, const float* __restrict__ W,
                                              int N, int K, EP ep) {
    __shared__ float As[16][64];
    __shared__ float Bs[16][64];
    const int tid = threadIdx.x;
    const int lr = tid >> 2, lk = tid & 3;
    const int tx = tid & 15, ty = tid >> 4;
    const int rowBase = blockIdx.y << 6;
    const int colBase = blockIdx.x << 6;
    float acc[4][4] = {};
    for (int kt = 0; kt < K; kt += 16) {
        float4 av = al.load(rowBase + lr, (kt >> 2) + lk);
        float4 bv = make_float4(0.f, 0.f, 0.f, 0.f);
        int n = colBase + lr;
        if (n < N) bv = *reinterpret_cast<const float4*>(W + n * K + kt + (lk << 2));
        __syncthreads();
        As[lk * 4 + 0][lr] = av.x; As[lk * 4 + 1][lr] = av.y;
        As[lk * 4 + 2][lr] = av.z; As[lk * 4 + 3][lr] = av.w;
        Bs[lk * 4 + 0][lr] = bv.x; Bs[lk * 4 + 1][lr] = bv.y;
        Bs[lk * 4 + 2][lr] = bv.z; Bs[lk * 4 + 3][lr] = bv.w;
        __syncthreads();
        #pragma unroll
        for (int k = 0; k < 16; k++) {
            float4 a = *reinterpret_cast<const float4*>(&As[k][ty << 2]);
            float4 b = *reinterpret_cast<const float4*>(&Bs[k][tx << 2]);
            float ar[4] = {a.x, a.y, a.z, a.w};
            float br[4] = {b.x, b.y, b.z, b.w};
            #pragma unroll
            for (int i = 0; i < 4; i++)
                #pragma unroll
                for (int j = 0; j < 4; j++)
                    acc[i][j] += ar[i] * br[j];
        }
    }
    #pragma unroll
    for (int i = 0; i < 4; i++) {
        int row = rowBase + (ty << 2) + i;
        #pragma unroll
        for (int j = 0; j < 4; j++) {
            int col = colBase + (tx << 2) + j;
            if (col < N) ep.run(row, col, acc[i][j]);
        }
    }
}

// ---------------------------------------------------------------------------
// K3: causal depthwise conv (D_CONV=4) + silu. One thread per (r,t,d).
// ---------------------------------------------------------------------------
__global__ void conv_kernel(const float* __restrict__ xz,
                            const float* __restrict__ cw, const float* __restrict__ cb,
                            float* __restrict__ xc) {
    int idx = blockIdx.x * 256 + threadIdx.x;    // ((r*4096+t)*256 + d)
    int d = idx & 255;
    int rt = idx >> 8;
    int t = rt & 4095;
    float acc = cb[d];
    const float* base = xz + rt * 512 + d;
    #pragma unroll
    for (int k = 0; k < 4; k++) {
        int tt = t - 3 + k;
        if (tt >= 0) acc += cw[d * 4 + k] * base[(k - 3) * 512];
    }
    xc[idx] = acc / (1.0f + fast_exp(-acc));     // silu
}

// ---------------------------------------------------------------------------
// K5: dt_proj + softplus, precompute e1 = exp(-delta), du = delta*u, silu(z).
// One block per (r,t) row; thread = d. All exps via FMA-pipe poly.
// ---------------------------------------------------------------------------
__global__ void dt_kernel(const float* __restrict__ xdbl, const float* __restrict__ xc,
                          const float* __restrict__ xz,
                          const float* __restrict__ dtw, const float* __restrict__ dtb,
                          float* __restrict__ e1o, float* __restrict__ duo,
                          float* __restrict__ szo) {
    int row = blockIdx.x;
    int d = threadIdx.x;
    __shared__ float sdt[8];
    if (d < 8) sdt[d] = xdbl[row * 40 + d];
    __syncthreads();
    float acc = dtb[d];
    #pragma unroll
    for (int j = 0; j < 8; j++) acc += sdt[j] * dtw[d * 8 + j];
    float delta = softplusf_(acc);
    int o = row * DI + d;
    e1o[o] = fast_exp(-delta);
    duo[o] = delta * xc[o];
    float z = xz[row * 512 + 256 + d];
    szo[o] = z / (1.0f + fast_exp(-z));
}

// ---------------------------------------------------------------------------
// Scan pass 1: per (r,chunk) block, thread=d. Compute chunk prod p and local
// end-state S. dA_n = e1^(n+1) via power table (A[d][n] == -(n+1) to 1 ulp;
// validity checked per thread with a generic fallback).
// ---------------------------------------------------------------------------
__global__ void __launch_bounds__(256) scan1_kernel(const float* __restrict__ xdbl,
                                                    const float* __restrict__ e1g,
                                                    const float* __restrict__ dug,
                                                    const float* __restrict__ A_log,
                                                    float* __restrict__ Sg,
                                                    float* __restrict__ pg) {
    int bid = blockIdx.x;               // r*32 + chunk
    int r = bid >> 5, chunk = bid & 31;
    int d = threadIdx.x;
    __shared__ float sB[CHUNK * DST];
    int rowBase = r * LQ + chunk * CHUNK;
    for (int i = d; i < CHUNK * DST; i += 256) {
        int st = i >> 4, n = i & 15;
        sB[i] = xdbl[(rowBase + st) * 40 + 8 + n];
    }
    bool fastok = true; float aRow[16];
    #pragma unroll
    for (int n = 0; n < 16; n++) {
        float a = fast_exp(A_log[d * 16 + n]);
        aRow[n] = -a;
        fastok = fastok && (fabsf(a - (float)(n + 1)) < 0.4f);
    }
    __syncthreads();
    float S[16];
    #pragma unroll
    for (int n = 0; n < 16; n++) S[n] = 0.f;
    float p = 1.f;
    const float* e1p = e1g + rowBase * DI + d;
    const float* dup = dug + rowBase * DI + d;
    if (fastok) {
        for (int st = 0; st < CHUNK; st++) {
            float e1 = e1p[st * DI], du = dup[st * DI];
            float e[17]; build_pows(e1, e);
            p *= e1;
            #pragma unroll
            for (int n = 0; n < 16; n++)
                S[n] = e[n + 1] * S[n] + du * sB[(st << 4) + n];
        }
    } else {
        for (int st = 0; st < CHUNK; st++) {
            float e1 = e1p[st * DI], du = dup[st * DI];
            float delta = -__logf(e1);
            p *= e1;
            #pragma unroll
            for (int n = 0; n < 16; n++)
                S[n] = fast_exp(aRow[n] * delta) * S[n] + du * sB[(st << 4) + n];
        }
    }
    int o = (bid * DI + d) * DST;
    #pragma unroll
    for (int n = 0; n < 16; n++) Sg[o + n] = S[n];
    pg[bid * DI + d] = p;
}

// Scan pass 2: carry scan across 32 chunks per (r,d). Emits chunk init states.
__global__ void scan2_kernel(const float* __restrict__ Sg, const float* __restrict__ pg,
                             const float* __restrict__ A_log, float* __restrict__ h0g) {
    int r = blockIdx.x;
    int d = threadIdx.x;
    bool fastok = true; float aRow[16];
    #pragma unroll
    for (int n = 0; n < 16; n++) {
        float a = fast_exp(A_log[d * 16 + n]);
        aRow[n] = -a;
        fastok = fastok && (fabsf(a - (float)(n + 1)) < 0.4f);
    }
    float H[16];
    #pragma unroll
    for (int n = 0; n < 16; n++) H[n] = 0.f;
    for (int c = 0; c < NCHUNK; c++) {
        int bid = r * NCHUNK + c;
        int o = (bid * DI + d) * DST;
        #pragma unroll
        for (int n = 0; n < 16; n++) h0g[o + n] = H[n];
        float p = pg[bid * DI + d];
        if (fastok) {
            float e[17]; build_pows(p, e);
            #pragma unroll
            for (int n = 0; n < 16; n++) H[n] = e[n + 1] * H[n] + Sg[o + n];
        } else {
            float lp = __logf(fmaxf(p, 1e-38f));
            #pragma unroll
            for (int n = 0; n < 16; n++)
                H[n] = fast_exp(aRow[n] * (-lp)) * H[n] + Sg[o + n];
        }
    }
}

// Scan pass 3: replay with correct init state, emit y = (C.h + u*D) * silu(z).
__global__ void __launch_bounds__(256) scan3_kernel(const float* __restrict__ xdbl,
                                                    const float* __restrict__ e1g,
                                                    const float* __restrict__ dug,
                                                    const float* __restrict__ xcg,
                                                    const float* __restrict__ szg,
                                                    const float* __restrict__ A_log,
                                                    const float* __restrict__ Dp,
                                                    const float* __restrict__ h0g,
                                                    float* __restrict__ yg) {
    int bid = blockIdx.x;
    int r = bid >> 5, chunk = bid & 31;
    int d = threadIdx.x;
    __shared__ float sB[CHUNK * DST];
    __shared__ float sC[CHUNK * DST];
    int rowBase = r * LQ + chunk * CHUNK;
    for (int i = d; i < CHUNK * DST; i += 256) {
        int st = i >> 4, n = i & 15;
        sB[i] = xdbl[(rowBase + st) * 40 + 8 + n];
        sC[i] = xdbl[(rowBase + st) * 40 + 24 + n];
    }
    bool fastok = true; float aRow[16];
    #pragma unroll
    for (int n = 0; n < 16; n++) {
        float a = fast_exp(A_log[d * 16 + n]);
        aRow[n] = -a;
        fastok = fastok && (fabsf(a - (float)(n + 1)) < 0.4f);
    }
    float h[16];
    {
        int o = (bid * DI + d) * DST;
        #pragma unroll
        for (int n = 0; n < 16; n++) h[n] = h0g[o + n];
    }
    float Dd = Dp[d];
    __syncthreads();
    const float* e1p = e1g + rowBase * DI + d;
    const float* dup = dug + rowBase * DI + d;
    const float* xcp = xcg + rowBase * DI + d;
    const float* szp = szg + rowBase * DI + d;
    float* yp = yg + rowBase * DI + d;
    if (fastok) {
        for (int st = 0; st < CHUNK; st++) {
            float e1 = e1p[st * DI], du = dup[st * DI];
            float u = xcp[st * DI], sz = szp[st * DI];
            float e[17]; build_pows(e1, e);
            float y0 = 0.f, y1 = 0.f, y2 = 0.f, y3 = 0.f;
            #pragma unroll
            for (int n = 0; n < 16; n++)
                h[n] = e[n + 1] * h[n] + du * sB[(st << 4) + n];
            #pragma unroll
            for (int n = 0; n < 16; n++) {
                float t = h[n] * sC[(st << 4) + n];
                if ((n & 3) == 0) y0 += t; else if ((n & 3) == 1) y1 += t;
                else if ((n & 3) == 2) y2 += t; else y3 += t;
            }
            float y = ((y0 + y1) + (y2 + y3)) + u * Dd;
            yp[st * DI] = y * sz;
        }
    } else {
        for (int st = 0; st < CHUNK; st++) {
            float e1 = e1p[st * DI], du = dup[st * DI];
            float u = xcp[st * DI], sz = szp[st * DI];
            float delta = -__logf(e1);
            float y = 0.f;
            #pragma unroll
            for (int n = 0; n < 16; n++) {
                h[n] = fast_exp(aRow[n] * delta) * h[n] + du * sB[(st << 4) + n];
                y += h[n] * sC[(st << 4) + n];
            }
            yp[st * DI] = (y + u * Dd) * sz;
        }
    }
}

// ---------------------------------------------------------------------------
// Host launch
// ---------------------------------------------------------------------------
extern "C" void kernel_launch(void* const* d_in, const int* in_sizes, int n_in,
                              void* d_out, int out_size) {
    const float* x        = (const float*)d_in[0];
    const float* ln_w     = (const float*)d_in[1];
    const float* ln_b     = (const float*)d_in[2];
    const float* mnorm_w  = (const float*)d_in[3];
    const float* mnorm_b  = (const float*)d_in[4];
    const float* in_proj_w= (const float*)d_in[5];
    const float* conv_w   = (const float*)d_in[6];
    const float* conv_b   = (const float*)d_in[7];
    const float* x_proj_w = (const float*)d_in[8];
    const float* dt_proj_w= (const float*)d_in[9];
    const float* dt_proj_b= (const float*)d_in[10];
    const float* A_log    = (const float*)d_in[11];
    const float* D_param  = (const float*)d_in[12];
    const float* out_proj_w=(const float*)d_in[13];
    const float* proj_w   = (const float*)d_in[14];
    const float* proj_b   = (const float*)d_in[15];
    const float* fc1_w    = (const float*)d_in[16];
    const float* fc1_b    = (const float*)d_in[17];
    const float* fc2_w    = (const float*)d_in[18];
    const float* fc2_b    = (const float*)d_in[19];

    float *norm, *xz, *xc, *xdbl, *e1, *du, *sz, *S, *p, *h0, *ygp, *y, *res, *hn, *fc1o;
    cudaGetSymbolAddress((void**)&norm, g_norm);
    cudaGetSymbolAddress((void**)&xz,   g_xz);
    cudaGetSymbolAddress((void**)&xc,   g_xc);
    cudaGetSymbolAddress((void**)&xdbl, g_xdbl);
    cudaGetSymbolAddress((void**)&e1,   g_e1);
    cudaGetSymbolAddress((void**)&du,   g_du);
    cudaGetSymbolAddress((void**)&sz,   g_sz);
    cudaGetSymbolAddress((void**)&S,    g_S);
    cudaGetSymbolAddress((void**)&p,    g_p);
    cudaGetSymbolAddress((void**)&h0,   g_h0);
    cudaGetSymbolAddress((void**)&ygp,  g_yg);
    cudaGetSymbolAddress((void**)&y,    g_y);
    cudaGetSymbolAddress((void**)&res,  g_res);
    cudaGetSymbolAddress((void**)&hn,   g_hn);
    cudaGetSymbolAddress((void**)&fc1o, g_fc1);

    // 1. double LN -> g_norm
    ln_in_kernel<<<512, 256>>>(x, ln_w, ln_b, mnorm_w, mnorm_b, norm);
    // 2. in_proj: (12288 x 512) = gather(norm) @ W^T
    gemm_k<<<dim3(8, 192), 256>>>(ALoadNormGather{norm}, in_proj_w, 512, 128,
                                  EpiStore{xz, 512});
    // 3. causal conv + silu -> g_xc
    conv_kernel<<<NROW * DI / 256, 256>>>(xz, conv_w, conv_b, xc);
    // 4. x_proj: (12288 x 40)
    gemm_k<<<dim3(1, 192), 256>>>(ALoadDirect{xc, 64}, x_proj_w, 40, 256,
                                  EpiStore{xdbl, 40});
    // 5. dt_proj + softplus + precompute e1/du/silu(z)
    dt_kernel<<<NROW, 256>>>(xdbl, xc, xz, dt_proj_w, dt_proj_b, e1, du, sz);
    // 6-8. chunked selective scan
    scan1_kernel<<<NSEQ * NCHUNK, 256>>>(xdbl, e1, du, A_log, S, p);
    scan2_kernel<<<NSEQ, 256>>>(S, p, A_log, h0);
    scan3_kernel<<<NSEQ * NCHUNK, 256>>>(xdbl, e1, du, xc, sz, A_log, D_param, h0, ygp);
    // 9. out_proj: (12288 x 128)
    gemm_k<<<dim3(2, 192), 256>>>(ALoadDirect{ygp, 64}, out_proj_w, 128, 256,
                                  EpiStore{y, 128});
    // 10. proj over concatenated directions + bias + x residual -> g_res
    gemm_k<<<dim3(2, 64), 256>>>(ALoadCat{y}, proj_w, 128, 384,
                                 EpiProjRes{res, proj_b, x});
    // 11. LN(res) -> g_hn
    ln_row_kernel<<<512, 256>>>(res, ln_w, ln_b, hn);
    // 12. fc1 + bias + gelu
    gemm_k<<<dim3(8, 64), 256>>>(ALoadDirect{hn, 32}, fc1_w, 512, 128,
                                 EpiBiasGelu{fc1o, fc1_b});
    // 13. fc2 + bias + residual, write channel-major output
    gemm_k<<<dim3(2, 64), 256>>>(ALoadDirect{fc1o, 128}, fc2_w, 128, 512,
                                 EpiFc2{(float*)d_out, fc2_b, res});
    (void)in_sizes; (void)n_in; (void)out_size;
}